// round 16
// baseline (speedup 1.0000x reference)
#include <cuda_runtime.h>

#define BB 4096
#define PB 2048    // big-batch f32x2 pairs (for XTh / Z rows)
#define BBS 800    // small (basis) batch: 784 basis + 1 zero + pad
#define PBS 400    // f32x2 pairs

// padded spatial layouts: S1 16x16 (14x14 interior), S2/S3 9x9 (7x7 interior)
constexpr int S1R = 32 * 256;   // 8192 rows
constexpr int S2R = 64 * 81;    // 5184 rows
constexpr int S4N = 256;
constexpr int RINT = 32 * 196 + 64 * 49 + 64 * 49 + 256;  // 12800 interior rows

typedef unsigned long long ull;

// ---------------- packed f32x2 helpers ----------------
__device__ __forceinline__ ull fma2(ull a, ull b, ull c) {
    ull d; asm("fma.rn.f32x2 %0, %1, %2, %3;" : "=l"(d) : "l"(a), "l"(b), "l"(c)); return d;
}
__device__ __forceinline__ ull add2(ull a, ull b) {
    ull d; asm("add.rn.f32x2 %0, %1, %2;" : "=l"(d) : "l"(a), "l"(b)); return d;
}
__device__ __forceinline__ ull mul2(ull a, ull b) {
    ull d; asm("mul.rn.f32x2 %0, %1, %2;" : "=l"(d) : "l"(a), "l"(b)); return d;
}
__device__ __forceinline__ ull pk(float x) {
    ull d; unsigned u = __float_as_uint(x);
    asm("mov.b64 %0, {%1, %1};" : "=l"(d) : "r"(u)); return d;
}
__device__ __forceinline__ ulonglong2 ld2(const ull* p) {
    return *reinterpret_cast<const ulonglong2*>(p);
}
__device__ __forceinline__ void st2(ull* p, ulonglong2 v) {
    *reinterpret_cast<ulonglong2*>(p) = v;
}

// ---------------- scratch (device globals; allocation-free) ----------------
// small (basis) relaxation state
__device__ float g_T1[2][S1R * BBS];
__device__ float g_T2[2][S2R * BBS];
__device__ float g_T3[2][S2R * BBS];
__device__ float g_T4[2][S4N * BBS];
__device__ float g_TD1[S1R * BBS];
__device__ float g_XTs[784 * BBS];
// centered compact matrices (cols 0..783 centered, 784 base, 785..799 stay .bss zero)
__device__ float g_A[RINT * 800];
__device__ float g_G[RINT * 800];
__device__ float g_Q1[800 * 800];
__device__ float g_Q2[800 * 800];
__device__ float g_Qe[800 * 800];
// big-batch eval
__device__ float g_XTh[800 * BB];   // x-hat transposed: rows 0..783 = x, 784 = 1, rest zero
__device__ float g_Z[800 * BB];     // Z = Qe * XTh
__device__ int   g_rowmap[RINT];
// weight layouts
__device__ float g_w2a[64 * 9 * 32];    // [o][t][c]
__device__ float g_w2b[32 * 9 * 64];    // [c][t][o]
__device__ float g_w3a[64 * 9 * 64];    // [o][t][m]
__device__ float g_w3b[64 * 9 * 64];    // [m][t][o]
__device__ float g_w4t[3136 * 256];     // [k][j]
__device__ float g_w4r[49 * 256 * 64];  // [pos][j][c]

// ---------------- init / prep ----------------
__global__ void zero_small() {
    int stride = gridDim.x * blockDim.x;
    float4 z = make_float4(0.f, 0.f, 0.f, 0.f);
    const int n1 = S1R * BBS / 4;
    const int n2 = S2R * BBS / 4;
    const int n4 = S4N * BBS / 4;
    for (int i = blockIdx.x * blockDim.x + threadIdx.x; i < n1; i += stride) {
        reinterpret_cast<float4*>(g_T1[0])[i] = z;
        reinterpret_cast<float4*>(g_T1[1])[i] = z;
        reinterpret_cast<float4*>(g_TD1)[i] = z;
        if (i < n2) {
            reinterpret_cast<float4*>(g_T2[0])[i] = z;
            reinterpret_cast<float4*>(g_T2[1])[i] = z;
            reinterpret_cast<float4*>(g_T3[0])[i] = z;
            reinterpret_cast<float4*>(g_T3[1])[i] = z;
        }
        if (i < n4) {
            reinterpret_cast<float4*>(g_T4[0])[i] = z;
            reinterpret_cast<float4*>(g_T4[1])[i] = z;
        }
    }
}

__global__ void basis_x() {
    int idx = blockIdx.x * 256 + threadIdx.x;       // over 784*BBS
    if (idx >= 784 * BBS) return;
    int p = idx / BBS, c = idx % BBS;
    g_XTs[idx] = (c < 784 && p == c) ? 1.f : 0.f;
}

__global__ void build_rowmap() {
    int r = blockIdx.x * 256 + threadIdx.x;
    if (r >= RINT) return;
    int pr;
    if (r < 6272) {
        int c = r / 196, t = r % 196;
        pr = c * 256 + (t / 14 + 1) * 16 + (t % 14 + 1);
    } else if (r < 9408) {
        int r2 = r - 6272; int c = r2 / 49, t = r2 % 49;
        pr = S1R + c * 81 + (t / 7 + 1) * 9 + (t % 7 + 1);
    } else if (r < 12544) {
        int r2 = r - 9408; int c = r2 / 49, t = r2 % 49;
        pr = S1R + S2R + c * 81 + (t / 7 + 1) * 9 + (t % 7 + 1);
    } else {
        pr = S1R + 2 * S2R + (r - 12544);
    }
    g_rowmap[r] = pr;
}

// transpose x into XTh rows 0..783; row 784 set by xh_one; rows 785+ stay zero
__global__ void transpose_x(const float* __restrict__ x) {
    __shared__ float tile[32][33];
    int p0 = blockIdx.x * 32, b0 = blockIdx.y * 32;
    int tx = threadIdx.x, ty = threadIdx.y;
    for (int i = ty; i < 32; i += 8) {
        int p = p0 + tx;
        tile[i][tx] = (p < 784) ? x[(b0 + i) * 784 + p] : 0.f;
    }
    __syncthreads();
    for (int i = ty; i < 32; i += 8) {
        int p = p0 + i;
        if (p < 784) g_XTh[p * BB + b0 + tx] = tile[tx][i];
    }
}

__global__ void xh_one() {
    int b = blockIdx.x * 256 + threadIdx.x;
    g_XTh[784 * BB + b] = 1.f;
}

__global__ void prep_weights(const float* __restrict__ w2,
                             const float* __restrict__ w3,
                             const float* __restrict__ w4) {
    int stride = gridDim.x * blockDim.x;
    for (int idx = blockIdx.x * blockDim.x + threadIdx.x; idx < 802816; idx += stride) {
        if (idx < 18432) {  // w2: [o=64][c=32][t=9]
            int o = idx / 288, r = idx % 288, c = r / 9, t = r % 9;
            float v = w2[idx];
            g_w2a[(o * 9 + t) * 32 + c] = v;
            g_w2b[(c * 9 + t) * 64 + o] = v;
        }
        if (idx < 36864) {  // w3: [m=64][o=64][t=9]
            int m = idx / 576, r = idx % 576, o = r / 9, t = r % 9;
            float v = w3[idx];
            g_w3a[(o * 9 + t) * 64 + m] = v;
            g_w3b[(m * 9 + t) * 64 + o] = v;
        }
        {   // w4: [j=256][k=3136]
            int j = idx / 3136, k = idx % 3136;
            float v = w4[idx];
            g_w4t[k * 256 + j] = v;
            int c = k / 49, pos = k % 49;
            g_w4r[(pos * 256 + j) * 64 + c] = v;
        }
    }
}

// d1 = conv1(x)+b1 — small (basis) batch
__global__ void compute_d1_small(const float* __restrict__ w1, const float* __restrict__ b1) {
    int b = blockIdx.x * 256 + threadIdx.x;
    if (b >= BBS) return;
    int pos = blockIdx.y;
    int u = pos / 14, v = pos % 14;
    int c = blockIdx.z;
    float acc = b1[c];
#pragma unroll
    for (int di = 0; di < 3; di++) {
        int h = 2 * u + di - 1;
        if (h < 0 || h >= 28) continue;
#pragma unroll
        for (int dj = 0; dj < 3; dj++) {
            int w = 2 * v + dj - 1;
            if (w < 0 || w >= 28) continue;
            acc = fmaf(w1[c * 9 + di * 3 + dj], g_XTs[(h * 28 + w) * BBS + b], acc);
        }
    }
    g_TD1[(c * 256 + (u + 1) * 16 + (v + 1)) * BBS + b] = acc;
}

// ============================================================================
// Fused relaxation step on the BASIS batch (PBS=400 pairs) — R15-proven.
// ============================================================================
#define STEP_SMEM 73728

#define ACC16(SV, WP) do {                                                     \
    _Pragma("unroll")                                                          \
    for (int _c = 0; _c < 16; _c++) {                                          \
        ull _w = (WP)[_c];                                                     \
        accA[_c] = fma2((SV).x, _w, accA[_c]);                                 \
        accB[_c] = fma2((SV).y, _w, accB[_c]);                                 \
    }                                                                          \
} while (0)

#define STAGE16D(DSTROW, SRCP) do {                                           \
    const float4* _s = reinterpret_cast<const float4*>(SRCP);                  \
    ull* _d = &wsu[(DSTROW) * 16];                                             \
    float4 _a = _s[0], _b = _s[1], _c = _s[2], _e = _s[3];                     \
    _d[0]  = pk(_a.x); _d[1]  = pk(_a.y); _d[2]  = pk(_a.z); _d[3]  = pk(_a.w);\
    _d[4]  = pk(_b.x); _d[5]  = pk(_b.y); _d[6]  = pk(_b.z); _d[7]  = pk(_b.w);\
    _d[8]  = pk(_c.x); _d[9]  = pk(_c.y); _d[10] = pk(_c.z); _d[11] = pk(_c.w);\
    _d[12] = pk(_e.x); _d[13] = pk(_e.y); _d[14] = pk(_e.z); _d[15] = pk(_e.w);\
} while (0)

__global__ void __launch_bounds__(256, 2) step_small(int cur,
                                                     const float* __restrict__ b2,
                                                     const float* __restrict__ b3,
                                                     const float* __restrict__ b4) {
    extern __shared__ ull wsu[];   // 576*16 ulls
    const int tid = threadIdx.x;
    const int bx = blockIdx.x;
    const ull half = pk(0.5f);
    const bool act = (tid < 200);

    const ull* __restrict__ S1c = (const ull*)g_T1[cur];
    ull* __restrict__ S1n = (ull*)g_T1[cur ^ 1];
    const ull* __restrict__ S2c = (const ull*)g_T2[cur];
    ull* __restrict__ S2n = (ull*)g_T2[cur ^ 1];
    const ull* __restrict__ S3c = (const ull*)g_T3[cur];
    ull* __restrict__ S3n = (ull*)g_T3[cur ^ 1];
    const ull* __restrict__ S4c = (const ull*)g_T4[cur];
    ull* __restrict__ S4n = (ull*)g_T4[cur ^ 1];
    const ull* __restrict__ D1p = (const ull*)g_TD1;

    ull accA[16], accB[16];
#pragma unroll
    for (int c = 0; c < 16; c++) { accA[c] = 0ull; accB[c] = 0ull; }

    if (bx < 16) {
        const int j0 = bx * 16;
        const int u = 2 * tid;

        for (int ch = 0; ch < 8; ch++) {
            __syncthreads();
            for (int i = tid; i < 392; i += 256) STAGE16D(i, &g_w4t[(ch * 392 + i) * 256 + j0]);
            __syncthreads();
            if (act) {
                for (int cc = 0; cc < 8; cc++) {
                    const ull* cb = S3c + ((ch * 8 + cc) * 81) * PBS + u;
                    const ull* wch = wsu + cc * 49 * 16;
                    int kk = 0;
#pragma unroll
                    for (int pp = 1; pp <= 7; pp++) {
#pragma unroll
                        for (int qq = 1; qq <= 7; qq++) {
                            ulonglong2 sv = ld2(cb + (pp * 9 + qq) * PBS);
                            ACC16(sv, wch + kk * 16); kk++;
                        }
                    }
                }
            }
        }

        if (act) {
#pragma unroll
            for (int c = 0; c < 16; c++) {
                int ii = (j0 + c) * PBS + u;
                ull bias = pk(b4[j0 + c]);
                ulonglong2 si = ld2(S4c + ii);
                ulonglong2 o;
                o.x = mul2(add2(add2(si.x, accA[c]), bias), half);
                o.y = mul2(add2(add2(si.y, accB[c]), bias), half);
                st2(S4n + ii, o);
            }
        }
    } else if (bx < 408) {
        int t = bx - 16;
        const int pos = t % 196;
        const int c0 = (t / 196) * 16;
        const int u_ = 2 * tid;

        for (int i = tid; i < 576; i += 256) STAGE16D(i, &g_w2a[i * 32 + c0]);
        __syncthreads();
        if (!act) return;

        const int uu = pos / 14, vv = pos % 14;
        int p0r, p1r, wu0, wu1;
        if (uu & 1) { p0r = ((uu + 1) >> 1) + 1; wu0 = 0;
                      p1r = ((uu - 1) >> 1) + 1; wu1 = 2; }
        else        { p0r = (uu >> 1) + 1;       wu0 = 1;
                      p1r = 8;                   wu1 = 0; }
        int q0r, q1r, wv0, wv1;
        if (vv & 1) { q0r = ((vv + 1) >> 1) + 1; wv0 = 0;
                      q1r = ((vv - 1) >> 1) + 1; wv1 = 2; }
        else        { q0r = (vv >> 1) + 1;       wv0 = 1;
                      q1r = 8;                   wv1 = 0; }

        const int off00 = (p0r * 9 + q0r) * PBS, wr00 = wu0 * 3 + wv0;
        const int off01 = (p0r * 9 + q1r) * PBS, wr01 = wu0 * 3 + wv1;
        const int off10 = (p1r * 9 + q0r) * PBS, wr10 = wu1 * 3 + wv0;
        const int off11 = (p1r * 9 + q1r) * PBS, wr11 = wu1 * 3 + wv1;

#pragma unroll 1
        for (int o = 0; o < 64; o++) {
            const ull* base = S2c + o * 81 * PBS + u_;
            const ull* wb = wsu + (o * 9) * 16;
            { ulonglong2 sv = ld2(base + off00); ACC16(sv, wb + wr00 * 16); }
            { ulonglong2 sv = ld2(base + off01); ACC16(sv, wb + wr01 * 16); }
            { ulonglong2 sv = ld2(base + off10); ACC16(sv, wb + wr10 * 16); }
            { ulonglong2 sv = ld2(base + off11); ACC16(sv, wb + wr11 * 16); }
        }

        const int obase = (uu + 1) * 16 + (vv + 1);
#pragma unroll
        for (int c = 0; c < 16; c++) {
            int ii = ((c0 + c) * 256 + obase) * PBS + u_;
            ulonglong2 si = ld2(S1c + ii), d1 = ld2(D1p + ii);
            ulonglong2 o;
            o.x = mul2(add2(add2(si.x, d1.x), accA[c]), half);
            o.y = mul2(add2(add2(si.y, d1.y), accB[c]), half);
            st2(S1n + ii, o);
        }
    } else if (bx < 604) {
        int t = bx - 408;
        const int pos = t % 49;
        const int o0 = (t / 49) * 16;
        const int u_ = 2 * tid;
        const int p = pos / 7, q = pos % 7;

        for (int i = tid; i < 288; i += 256) STAGE16D(i, &g_w2b[i * 64 + o0]);
        for (int i = tid; i < 288; i += 256) STAGE16D(288 + i, &g_w3b[i * 64 + o0]);
        __syncthreads();

        int offc[9], offt[9];
#pragma unroll
        for (int di = 0; di < 3; di++)
#pragma unroll
            for (int dj = 0; dj < 3; dj++) {
                offc[di * 3 + dj] = ((2 * p + di) * 16 + (2 * q + dj)) * PBS;
                offt[di * 3 + dj] = ((p + 2 - di) * 9 + (q + 2 - dj)) * PBS;
            }

        if (act) {
#pragma unroll 1
            for (int c = 0; c < 32; c++) {
                const ull* base = S1c + c * 256 * PBS + u_;
                const ull* wb = wsu + (c * 9) * 16;
#pragma unroll
                for (int t2 = 0; t2 < 9; t2++) {
                    ulonglong2 sv = ld2(base + offc[t2]);
                    ACC16(sv, wb + t2 * 16);
                }
            }
#pragma unroll 1
            for (int m = 0; m < 32; m++) {
                const ull* base = S3c + m * 81 * PBS + u_;
                const ull* wb = wsu + (288 + m * 9) * 16;
#pragma unroll
                for (int t2 = 0; t2 < 9; t2++) {
                    ulonglong2 sv = ld2(base + offt[t2]);
                    ACC16(sv, wb + t2 * 16);
                }
            }
        }
        __syncthreads();
        for (int i = tid; i < 288; i += 256) STAGE16D(i, &g_w3b[(288 + i) * 64 + o0]);
        __syncthreads();
        if (!act) return;
#pragma unroll 1
        for (int m = 32; m < 64; m++) {
            const ull* base = S3c + m * 81 * PBS + u_;
            const ull* wb = wsu + ((m - 32) * 9) * 16;
#pragma unroll
            for (int t2 = 0; t2 < 9; t2++) {
                ulonglong2 sv = ld2(base + offt[t2]);
                ACC16(sv, wb + t2 * 16);
            }
        }

        const int obase = (p + 1) * 9 + (q + 1);
#pragma unroll
        for (int c = 0; c < 16; c++) {
            int ii = ((o0 + c) * 81 + obase) * PBS + u_;
            ull bias = pk(b2[o0 + c]);
            ulonglong2 si = ld2(S2c + ii);
            ulonglong2 o;
            o.x = mul2(add2(add2(si.x, accA[c]), bias), half);
            o.y = mul2(add2(add2(si.y, accB[c]), bias), half);
            st2(S2n + ii, o);
        }
    } else {
        int t = bx - 604;
        const int pos = t % 49;
        const int c0 = (t / 49) * 16;
        const int u_ = 2 * tid;
        const int p = pos / 7, q = pos % 7;

        for (int i = tid; i < 576; i += 256) STAGE16D(i, &g_w3a[i * 64 + c0]);
        __syncthreads();

        if (act) {
            int off[9];
#pragma unroll
            for (int di = 0; di < 3; di++)
#pragma unroll
                for (int dj = 0; dj < 3; dj++)
                    off[di * 3 + dj] = ((p + di) * 9 + (q + dj)) * PBS;
#pragma unroll 1
            for (int o = 0; o < 64; o++) {
                const ull* base = S2c + o * 81 * PBS + u_;
                const ull* wb = wsu + (o * 9) * 16;
#pragma unroll
                for (int t2 = 0; t2 < 9; t2++) {
                    ulonglong2 sv = ld2(base + off[t2]);
                    ACC16(sv, wb + t2 * 16);
                }
            }
        }
        __syncthreads();
        for (int j = tid; j < 256; j += 256) STAGE16D(j, &g_w4r[(pos * 256 + j) * 64 + c0]);
        __syncthreads();
        if (!act) return;
#pragma unroll 1
        for (int j = 0; j < 256; j++) {
            ulonglong2 sv = ld2(S4c + j * PBS + u_);
            ACC16(sv, wsu + j * 16);
        }

        const int obase = (p + 1) * 9 + (q + 1);
#pragma unroll
        for (int c = 0; c < 16; c++) {
            int ii = ((c0 + c) * 81 + obase) * PBS + u_;
            ull bias = pk(b3[c0 + c]);
            ulonglong2 si = ld2(S3c + ii);
            ulonglong2 o;
            o.x = mul2(add2(add2(si.x, accA[c]), bias), half);
            o.y = mul2(add2(add2(si.y, accB[c]), bias), half);
            st2(S3n + ii, o);
        }
    }
}

// ============================================================================
// Small-batch forward kernels: drive = (fwd of final basis states), into [1]
// ============================================================================
__global__ void __launch_bounds__(256) fwd2s(const float* __restrict__ b2) {
    __shared__ float ws2[288 * 8];
    const int tid = threadIdx.x;
    const int o0 = blockIdx.z * 8;
    for (int i = tid; i < 288; i += 256) {
        const float* src = &g_w2b[i * 64 + o0];
        float* dst = &ws2[i * 8];
#pragma unroll
        for (int r = 0; r < 8; r++) dst[r] = src[r];
    }
    __syncthreads();

    const int bp = blockIdx.x * 256 + tid;
    if (bp >= PBS) return;
    const int pos = blockIdx.y;
    const int p = pos / 7, q = pos % 7;

    ull acc[8];
#pragma unroll
    for (int r = 0; r < 8; r++) acc[r] = 0ull;

    int off[9];
#pragma unroll
    for (int di = 0; di < 3; di++)
#pragma unroll
        for (int dj = 0; dj < 3; dj++)
            off[di * 3 + dj] = ((2 * p + di) * 16 + (2 * q + dj)) * PBS;
    const ull* __restrict__ S1 = (const ull*)g_T1[0];
#pragma unroll 2
    for (int c = 0; c < 32; c++) {
        const ull* base = S1 + c * 256 * PBS + bp;
        const float* wb = ws2 + c * 72;
#pragma unroll
        for (int t = 0; t < 9; t++) {
            ull sv = base[off[t]];
            const float* wp = wb + t * 8;
#pragma unroll
            for (int r = 0; r < 8; r++) acc[r] = fma2(sv, pk(wp[r]), acc[r]);
        }
    }

    ull* __restrict__ outp = (ull*)g_T2[1];
    const int oidx = (o0 * 81 + (p + 1) * 9 + (q + 1)) * PBS + bp;
#pragma unroll
    for (int r = 0; r < 8; r++) outp[oidx + r * (81 * PBS)] = add2(acc[r], pk(b2[o0 + r]));
}

__global__ void __launch_bounds__(256) fwd3s(const float* __restrict__ b3) {
    __shared__ ull ws3[576 * 8];
    const int tid = threadIdx.x;
    const int c0 = blockIdx.z * 8;
    const int pos = blockIdx.y;
    for (int i = tid; i < 576; i += 256) {
        const float* src = &g_w3a[i * 64 + c0];
        ull* dst = &ws3[i * 8];
#pragma unroll
        for (int r = 0; r < 8; r++) dst[r] = pk(src[r]);
    }
    __syncthreads();

    const int bp = blockIdx.x * 256 + tid;
    if (bp >= PBS) return;
    const int p = pos / 7, q = pos % 7;

    ull acc[8];
#pragma unroll
    for (int r = 0; r < 8; r++) acc[r] = 0ull;

    int off[9];
#pragma unroll
    for (int di = 0; di < 3; di++)
#pragma unroll
        for (int dj = 0; dj < 3; dj++)
            off[di * 3 + dj] = ((p + di) * 9 + (q + dj)) * PBS;
    const ull* __restrict__ S2 = (const ull*)g_T2[0];
#pragma unroll 2
    for (int o = 0; o < 64; o++) {
        const ull* base = S2 + o * 81 * PBS + bp;
        const ull* wb = ws3 + o * 72;
#pragma unroll
        for (int t = 0; t < 9; t++) {
            ull sv = base[off[t]];
            const ull* wp = wb + t * 8;
#pragma unroll
            for (int r = 0; r < 8; r++) acc[r] = fma2(sv, wp[r], acc[r]);
        }
    }

    ull* __restrict__ outp = (ull*)g_T3[1];
    const int oidx = (c0 * 81 + (p + 1) * 9 + (q + 1)) * PBS + bp;
#pragma unroll
    for (int r = 0; r < 8; r++) outp[oidx + r * (81 * PBS)] = add2(acc[r], pk(b3[c0 + r]));
}

__global__ void __launch_bounds__(256) fwd4s(const float* __restrict__ b4) {
    __shared__ ull ws[392 * 8];
    const int tid = threadIdx.x;
    const int j0 = blockIdx.y * 8;
    const int bp = blockIdx.x * 256 + tid;
    const bool act = (bp < PBS);
    const ull* __restrict__ S3 = (const ull*)g_T3[0];

    ull acc[8];
#pragma unroll
    for (int r = 0; r < 8; r++) acc[r] = 0ull;

    for (int ch = 0; ch < 8; ch++) {
        __syncthreads();
        for (int i = tid; i < 392; i += 256) {
            const float* src = &g_w4t[(ch * 392 + i) * 256 + j0];
            ull* dst = &ws[i * 8];
#pragma unroll
            for (int r = 0; r < 8; r++) dst[r] = pk(src[r]);
        }
        __syncthreads();
        if (act) {
            for (int cc = 0; cc < 8; cc++) {
                const ull* cb = S3 + ((ch * 8 + cc) * 81) * PBS + bp;
                const ull* wch = ws + cc * 392;
                int kk = 0;
#pragma unroll
                for (int pp = 1; pp <= 7; pp++) {
#pragma unroll
                    for (int qq = 1; qq <= 7; qq++) {
                        ull sv = cb[(pp * 9 + qq) * PBS];
                        const ull* wp = wch + kk * 8; kk++;
#pragma unroll
                        for (int r = 0; r < 8; r++) acc[r] = fma2(sv, wp[r], acc[r]);
                    }
                }
            }
        }
    }

    if (!act) return;
    ull* __restrict__ outp = (ull*)g_T4[1];
#pragma unroll
    for (int r = 0; r < 8; r++) outp[(j0 + r) * PBS + bp] = add2(acc[r], pk(b4[j0 + r]));
}

// ---------------- centered compact matrices A (states) and G (drives) -------
__device__ __forceinline__ float state_read(int pr, int c) {
    if (pr < S1R) return g_T1[0][pr * BBS + c];
    if (pr < S1R + S2R) return g_T2[0][(pr - S1R) * BBS + c];
    if (pr < S1R + 2 * S2R) return g_T3[0][(pr - S1R - S2R) * BBS + c];
    return g_T4[0][(pr - S1R - 2 * S2R) * BBS + c];
}
__device__ __forceinline__ float drive_read(int pr, int c) {
    if (pr < S1R) return g_TD1[pr * BBS + c];
    if (pr < S1R + S2R) return g_T2[1][(pr - S1R) * BBS + c];
    if (pr < S1R + 2 * S2R) return g_T3[1][(pr - S1R - S2R) * BBS + c];
    return g_T4[1][(pr - S1R - 2 * S2R) * BBS + c];
}

__global__ void build_AG() {
    int idx = blockIdx.x * 256 + threadIdx.x;   // over RINT*785
    if (idx >= RINT * 785) return;
    int r = idx / 785, j = idx % 785;
    int pr = g_rowmap[r];
    float s0 = state_read(pr, 784);
    float d0 = drive_read(pr, 784);
    if (j < 784) {
        g_A[r * 800 + j] = state_read(pr, j) - s0;
        g_G[r * 800 + j] = drive_read(pr, j) - d0;
    } else {
        g_A[r * 800 + 784] = s0;
        g_G[r * 800 + 784] = d0;
    }
}

// ---------------- Gram GEMM: C = A^T B  (800x800, K = RINT) -----------------
// which=0: C=Q1, B=A;  which=1: C=Q2, B=G
__global__ void __launch_bounds__(256) gram_kernel(int which) {
    __shared__ float As[16][64], Bs[16][64];
    const float* __restrict__ A = g_A;
    const float* __restrict__ B = (which == 0) ? g_A : g_G;
    float* __restrict__ C = (which == 0) ? g_Q1 : g_Q2;
    const int tid = threadIdx.x;
    const int ti = tid / 16, tj = tid % 16;
    const int i0 = blockIdx.y * 64, j0 = blockIdx.x * 64;

    ull acc[4][2];
#pragma unroll
    for (int i = 0; i < 4; i++) { acc[i][0] = 0ull; acc[i][1] = 0ull; }

    for (int k0 = 0; k0 < RINT; k0 += 16) {
        __syncthreads();
        for (int t = tid; t < 1024; t += 256) {
            int kr = t / 64, c = t % 64;
            int ca = i0 + c, cb = j0 + c;
            As[kr][c] = (ca < 800) ? A[(k0 + kr) * 800 + ca] : 0.f;
            Bs[kr][c] = (cb < 800) ? B[(k0 + kr) * 800 + cb] : 0.f;
        }
        __syncthreads();
#pragma unroll 4
        for (int k = 0; k < 16; k++) {
            const float* ar = &As[k][ti * 4];
            const ull* br = reinterpret_cast<const ull*>(&Bs[k][tj * 4]);
            ull b0 = br[0], b1 = br[1];
#pragma unroll
            for (int i = 0; i < 4; i++) {
                ull av = pk(ar[i]);
                acc[i][0] = fma2(av, b0, acc[i][0]);
                acc[i][1] = fma2(av, b1, acc[i][1]);
            }
        }
    }

#pragma unroll
    for (int i = 0; i < 4; i++) {
        int row = i0 + ti * 4 + i;
        int col = j0 + tj * 4;
        if (row < 800 && col < 800) {
            ull* dst = reinterpret_cast<ull*>(&C[row * 800 + col]);
            dst[0] = acc[i][0];
            dst[1] = acc[i][1];
        }
    }
}

__global__ void combine_q() {
    int idx = blockIdx.x * 256 + threadIdx.x;
    if (idx >= 800 * 800) return;
    g_Qe[idx] = 0.5f * g_Q1[idx] - g_Q2[idx];
}

// ---------------- Z = Qe * XTh  (800 x 4096) ----------------
__global__ void __launch_bounds__(256) zgemm() {
    __shared__ ull smw[200 * 16];    // 25.6 KB
    const int tid = threadIdx.x;
    const int bx = blockIdx.x;
    const int bslice = bx & 3;
    const int row0 = (bx >> 2) * 16;
    const int u = bslice * 512 + 2 * tid;

    ull accA[16], accB[16];
#pragma unroll
    for (int c = 0; c < 16; c++) { accA[c] = 0ull; accB[c] = 0ull; }

    const ull* __restrict__ XT2 = (const ull*)g_XTh;
    for (int ch = 0; ch < 4; ch++) {
        __syncthreads();
        for (int idx = tid; idx < 16 * 200; idx += 256) {
            int r = idx / 200, k = idx % 200;
            smw[k * 16 + r] = pk(g_Qe[(row0 + r) * 800 + ch * 200 + k]);
        }
        __syncthreads();
#pragma unroll 1
        for (int k = 0; k < 200; k++) {
            ulonglong2 sv = ld2(XT2 + (ch * 200 + k) * PB + u);
            const ull* wp = &smw[k * 16];
            ACC16(sv, wp);
        }
    }

    ull* __restrict__ Z = (ull*)g_Z;
#pragma unroll
    for (int c = 0; c < 16; c++) {
        ulonglong2 o; o.x = accA[c]; o.y = accB[c];
        st2(Z + (row0 + c) * PB + u, o);
    }
}

// ---------------- final energy: E = 0.5|x|^2 - vb.x + xh^T Qe xh ------------
__global__ void energy_final(const float* __restrict__ vb, float* __restrict__ out) {
    int b = blockIdx.x * 256 + threadIdx.x;
    double e = 0.0;
    for (int i = 0; i < 784; i++) {
        float xv = g_XTh[i * BB + b];
        float term = xv * (0.5f * xv - vb[i] + g_Z[i * BB + b]);
        e += (double)term;
    }
    e += (double)g_Z[784 * BB + b];
    out[b] = (float)e;
}

// ---------------- launcher ----------------
extern "C" void kernel_launch(void* const* d_in, const int* in_sizes, int n_in,
                              void* d_out, int out_size) {
    const float* x  = (const float*)d_in[0];
    const float* vb = (const float*)d_in[1];
    const float* w1 = (const float*)d_in[2];
    const float* b1 = (const float*)d_in[3];
    const float* w2 = (const float*)d_in[4];
    const float* b2 = (const float*)d_in[5];
    const float* w3 = (const float*)d_in[6];
    const float* b3 = (const float*)d_in[7];
    const float* w4 = (const float*)d_in[8];
    const float* b4 = (const float*)d_in[9];
    float* out = (float*)d_out;

    cudaFuncSetAttribute(step_small, cudaFuncAttributeMaxDynamicSharedMemorySize, STEP_SMEM);

    zero_small<<<2048, 256>>>();
    basis_x<<<(784 * BBS + 255) / 256, 256>>>();
    build_rowmap<<<(RINT + 255) / 256, 256>>>();
    transpose_x<<<dim3(25, 128), dim3(32, 8)>>>(x);
    xh_one<<<16, 256>>>();
    prep_weights<<<1024, 256>>>(w2, w3, w4);
    compute_d1_small<<<dim3((BBS + 255) / 256, 196, 32), 256>>>(w1, b1);

    // 50-step relaxation on 784 basis images + zero image (final in buffer 0)
    int cs = 0;
    for (int t = 0; t < 50; t++) {
        step_small<<<800, 256, STEP_SMEM>>>(cs, b2, b3, b4);
        cs ^= 1;
    }

    // drive vectors: forward pass of final basis states into buffers [1]
    fwd2s<<<dim3(2, 49, 8), 256>>>(b2);
    fwd3s<<<dim3(2, 49, 8), 256>>>(b3);
    fwd4s<<<dim3(2, 32, 1), 256>>>(b4);

    // quadratic form assembly: Q1 = A^T A, Q2 = A^T G, Qe = 0.5 Q1 - Q2
    build_AG<<<(RINT * 785 + 255) / 256, 256>>>();
    gram_kernel<<<dim3(13, 13), 256>>>(0);
    gram_kernel<<<dim3(13, 13), 256>>>(1);
    combine_q<<<(800 * 800 + 255) / 256, 256>>>();

    // evaluate: Z = Qe * XTh, then E_b per sample
    zgemm<<<(800 / 16) * 4, 256>>>();
    energy_final<<<16, 256>>>(vb, out);
}

// round 17
// speedup vs baseline: 1.0402x; 1.0402x over previous
#include <cuda_runtime.h>

#define BB 4096
#define PB 2048    // big-batch f32x2 pairs (for XTh / Z rows)
#define BBS 800    // small (basis) batch: 784 basis + 1 zero + pad
#define PBS 400    // f32x2 pairs

// padded spatial layouts: S1 16x16 (14x14 interior), S2/S3 9x9 (7x7 interior)
constexpr int S1R = 32 * 256;   // 8192 rows
constexpr int S2R = 64 * 81;    // 5184 rows
constexpr int S4N = 256;
constexpr int RINT = 32 * 196 + 64 * 49 + 64 * 49 + 256;  // 12800 interior rows

typedef unsigned long long ull;

// ---------------- packed f32x2 helpers ----------------
__device__ __forceinline__ ull fma2(ull a, ull b, ull c) {
    ull d; asm("fma.rn.f32x2 %0, %1, %2, %3;" : "=l"(d) : "l"(a), "l"(b), "l"(c)); return d;
}
__device__ __forceinline__ ull add2(ull a, ull b) {
    ull d; asm("add.rn.f32x2 %0, %1, %2;" : "=l"(d) : "l"(a), "l"(b)); return d;
}
__device__ __forceinline__ ull mul2(ull a, ull b) {
    ull d; asm("mul.rn.f32x2 %0, %1, %2;" : "=l"(d) : "l"(a), "l"(b)); return d;
}
__device__ __forceinline__ ull pk(float x) {
    ull d; unsigned u = __float_as_uint(x);
    asm("mov.b64 %0, {%1, %1};" : "=l"(d) : "r"(u)); return d;
}
__device__ __forceinline__ ulonglong2 ld2(const ull* p) {
    return *reinterpret_cast<const ulonglong2*>(p);
}
__device__ __forceinline__ void st2(ull* p, ulonglong2 v) {
    *reinterpret_cast<ulonglong2*>(p) = v;
}

// ---------------- scratch (device globals; allocation-free) ----------------
// small (basis) relaxation state
__device__ float g_T1[2][S1R * BBS];
__device__ float g_T2[2][S2R * BBS];
__device__ float g_T3[2][S2R * BBS];
__device__ float g_T4[2][S4N * BBS];
__device__ float g_TD1[S1R * BBS];
__device__ float g_XTs[784 * BBS];
// centered compact matrices (cols 0..783 centered, 784 base, 785..799 stay .bss zero)
__device__ float g_A[RINT * 800];
__device__ float g_H[RINT * 800];      // H = 0.5*A - G  (G = centered drives)
__device__ float g_Qe[800 * 800];      // Qe = A^T H
// big-batch eval
__device__ float g_XTh[800 * BB];   // x-hat transposed: rows 0..783 = x, 784 = 1, rest zero
__device__ float g_Z[800 * BB];     // Z = Qe * XTh
__device__ int   g_rowmap[RINT];
// weight layouts
__device__ float g_w2a[64 * 9 * 32];    // [o][t][c]
__device__ float g_w2b[32 * 9 * 64];    // [c][t][o]
__device__ float g_w3a[64 * 9 * 64];    // [o][t][m]
__device__ float g_w3b[64 * 9 * 64];    // [m][t][o]
__device__ float g_w4t[3136 * 256];     // [k][j]
__device__ float g_w4r[49 * 256 * 64];  // [pos][j][c]

// ---------------- init / prep ----------------
__global__ void zero_small() {
    int stride = gridDim.x * blockDim.x;
    float4 z = make_float4(0.f, 0.f, 0.f, 0.f);
    const int n1 = S1R * BBS / 4;
    const int n2 = S2R * BBS / 4;
    const int n4 = S4N * BBS / 4;
    for (int i = blockIdx.x * blockDim.x + threadIdx.x; i < n1; i += stride) {
        reinterpret_cast<float4*>(g_T1[0])[i] = z;
        reinterpret_cast<float4*>(g_T1[1])[i] = z;
        reinterpret_cast<float4*>(g_TD1)[i] = z;
        if (i < n2) {
            reinterpret_cast<float4*>(g_T2[0])[i] = z;
            reinterpret_cast<float4*>(g_T2[1])[i] = z;
            reinterpret_cast<float4*>(g_T3[0])[i] = z;
            reinterpret_cast<float4*>(g_T3[1])[i] = z;
        }
        if (i < n4) {
            reinterpret_cast<float4*>(g_T4[0])[i] = z;
            reinterpret_cast<float4*>(g_T4[1])[i] = z;
        }
    }
}

__global__ void basis_x() {
    int idx = blockIdx.x * 256 + threadIdx.x;       // over 784*BBS
    if (idx >= 784 * BBS) return;
    int p = idx / BBS, c = idx % BBS;
    g_XTs[idx] = (c < 784 && p == c) ? 1.f : 0.f;
}

__global__ void build_rowmap() {
    int r = blockIdx.x * 256 + threadIdx.x;
    if (r >= RINT) return;
    int pr;
    if (r < 6272) {
        int c = r / 196, t = r % 196;
        pr = c * 256 + (t / 14 + 1) * 16 + (t % 14 + 1);
    } else if (r < 9408) {
        int r2 = r - 6272; int c = r2 / 49, t = r2 % 49;
        pr = S1R + c * 81 + (t / 7 + 1) * 9 + (t % 7 + 1);
    } else if (r < 12544) {
        int r2 = r - 9408; int c = r2 / 49, t = r2 % 49;
        pr = S1R + S2R + c * 81 + (t / 7 + 1) * 9 + (t % 7 + 1);
    } else {
        pr = S1R + 2 * S2R + (r - 12544);
    }
    g_rowmap[r] = pr;
}

// transpose x into XTh rows 0..783; row 784 set by xh_one; rows 785+ stay zero
__global__ void transpose_x(const float* __restrict__ x) {
    __shared__ float tile[32][33];
    int p0 = blockIdx.x * 32, b0 = blockIdx.y * 32;
    int tx = threadIdx.x, ty = threadIdx.y;
    for (int i = ty; i < 32; i += 8) {
        int p = p0 + tx;
        tile[i][tx] = (p < 784) ? x[(b0 + i) * 784 + p] : 0.f;
    }
    __syncthreads();
    for (int i = ty; i < 32; i += 8) {
        int p = p0 + i;
        if (p < 784) g_XTh[p * BB + b0 + tx] = tile[tx][i];
    }
}

__global__ void xh_one() {
    int b = blockIdx.x * 256 + threadIdx.x;
    g_XTh[784 * BB + b] = 1.f;
}

__global__ void prep_weights(const float* __restrict__ w2,
                             const float* __restrict__ w3,
                             const float* __restrict__ w4) {
    int stride = gridDim.x * blockDim.x;
    for (int idx = blockIdx.x * blockDim.x + threadIdx.x; idx < 802816; idx += stride) {
        if (idx < 18432) {  // w2: [o=64][c=32][t=9]
            int o = idx / 288, r = idx % 288, c = r / 9, t = r % 9;
            float v = w2[idx];
            g_w2a[(o * 9 + t) * 32 + c] = v;
            g_w2b[(c * 9 + t) * 64 + o] = v;
        }
        if (idx < 36864) {  // w3: [m=64][o=64][t=9]
            int m = idx / 576, r = idx % 576, o = r / 9, t = r % 9;
            float v = w3[idx];
            g_w3a[(o * 9 + t) * 64 + m] = v;
            g_w3b[(m * 9 + t) * 64 + o] = v;
        }
        {   // w4: [j=256][k=3136]
            int j = idx / 3136, k = idx % 3136;
            float v = w4[idx];
            g_w4t[k * 256 + j] = v;
            int c = k / 49, pos = k % 49;
            g_w4r[(pos * 256 + j) * 64 + c] = v;
        }
    }
}

// d1 = conv1(x)+b1 — small (basis) batch
__global__ void compute_d1_small(const float* __restrict__ w1, const float* __restrict__ b1) {
    int b = blockIdx.x * 256 + threadIdx.x;
    if (b >= BBS) return;
    int pos = blockIdx.y;
    int u = pos / 14, v = pos % 14;
    int c = blockIdx.z;
    float acc = b1[c];
#pragma unroll
    for (int di = 0; di < 3; di++) {
        int h = 2 * u + di - 1;
        if (h < 0 || h >= 28) continue;
#pragma unroll
        for (int dj = 0; dj < 3; dj++) {
            int w = 2 * v + dj - 1;
            if (w < 0 || w >= 28) continue;
            acc = fmaf(w1[c * 9 + di * 3 + dj], g_XTs[(h * 28 + w) * BBS + b], acc);
        }
    }
    g_TD1[(c * 256 + (u + 1) * 16 + (v + 1)) * BBS + b] = acc;
}

// ============================================================================
// Fused relaxation step on the BASIS batch (PBS=400 pairs).
// K4 split into 32 blocks (16 j-groups x 2 batch-halves) to kill the straggler.
// Grid = 816: [0,32): k4   [32,424): k1   [424,620): k2   [620,816): k3
// ============================================================================
#define STEP_SMEM 73728
#define STEP_GRID 816

#define ACC16(SV, WP) do {                                                     \
    _Pragma("unroll")                                                          \
    for (int _c = 0; _c < 16; _c++) {                                          \
        ull _w = (WP)[_c];                                                     \
        accA[_c] = fma2((SV).x, _w, accA[_c]);                                 \
        accB[_c] = fma2((SV).y, _w, accB[_c]);                                 \
    }                                                                          \
} while (0)

#define ACC16S(SV, WP) do {                                                    \
    _Pragma("unroll")                                                          \
    for (int _c = 0; _c < 16; _c++) {                                          \
        accA[_c] = fma2((SV), (WP)[_c], accA[_c]);                             \
    }                                                                          \
} while (0)

#define STAGE16D(DSTROW, SRCP) do {                                           \
    const float4* _s = reinterpret_cast<const float4*>(SRCP);                  \
    ull* _d = &wsu[(DSTROW) * 16];                                             \
    float4 _a = _s[0], _b = _s[1], _c = _s[2], _e = _s[3];                     \
    _d[0]  = pk(_a.x); _d[1]  = pk(_a.y); _d[2]  = pk(_a.z); _d[3]  = pk(_a.w);\
    _d[4]  = pk(_b.x); _d[5]  = pk(_b.y); _d[6]  = pk(_b.z); _d[7]  = pk(_b.w);\
    _d[8]  = pk(_c.x); _d[9]  = pk(_c.y); _d[10] = pk(_c.z); _d[11] = pk(_c.w);\
    _d[12] = pk(_e.x); _d[13] = pk(_e.y); _d[14] = pk(_e.z); _d[15] = pk(_e.w);\
} while (0)

__global__ void __launch_bounds__(256, 2) step_small(int cur,
                                                     const float* __restrict__ b2,
                                                     const float* __restrict__ b3,
                                                     const float* __restrict__ b4) {
    extern __shared__ ull wsu[];   // 576*16 ulls
    const int tid = threadIdx.x;
    const int bx = blockIdx.x;
    const ull hlf = pk(0.5f);
    const bool act = (tid < 200);

    const ull* __restrict__ S1c = (const ull*)g_T1[cur];
    ull* __restrict__ S1n = (ull*)g_T1[cur ^ 1];
    const ull* __restrict__ S2c = (const ull*)g_T2[cur];
    ull* __restrict__ S2n = (ull*)g_T2[cur ^ 1];
    const ull* __restrict__ S3c = (const ull*)g_T3[cur];
    ull* __restrict__ S3n = (ull*)g_T3[cur ^ 1];
    const ull* __restrict__ S4c = (const ull*)g_T4[cur];
    ull* __restrict__ S4n = (ull*)g_T4[cur ^ 1];
    const ull* __restrict__ D1p = (const ull*)g_TD1;

    ull accA[16], accB[16];
#pragma unroll
    for (int c = 0; c < 16; c++) { accA[c] = 0ull; accB[c] = 0ull; }

    if (bx < 32) {
        // -------- K4: s4' = 0.5*(s4 + W4 s3 + b4); 2 batch-halves --------
        const int j0 = (bx >> 1) * 16;
        const int bh = bx & 1;
        const int u = bh * 200 + tid;   // one ull pair per thread (tid<200)

        for (int ch = 0; ch < 8; ch++) {
            __syncthreads();
            for (int i = tid; i < 392; i += 256) STAGE16D(i, &g_w4t[(ch * 392 + i) * 256 + j0]);
            __syncthreads();
            if (act) {
                for (int cc = 0; cc < 8; cc++) {
                    const ull* cb = S3c + ((ch * 8 + cc) * 81) * PBS + u;
                    const ull* wch = wsu + cc * 49 * 16;
                    int kk = 0;
#pragma unroll
                    for (int pp = 1; pp <= 7; pp++) {
#pragma unroll
                        for (int qq = 1; qq <= 7; qq++) {
                            ull sv = cb[(pp * 9 + qq) * PBS];
                            ACC16S(sv, wch + kk * 16); kk++;
                        }
                    }
                }
            }
        }

        if (act) {
#pragma unroll
            for (int c = 0; c < 16; c++) {
                int ii = (j0 + c) * PBS + u;
                ull bias = pk(b4[j0 + c]);
                S4n[ii] = mul2(add2(add2(S4c[ii], accA[c]), bias), hlf);
            }
        }
    } else if (bx < 424) {
        // ---------------- K1: s1' = 0.5*(s1 + d1 + tconv2(s2)) ----------------
        int t = bx - 32;
        const int pos = t % 196;
        const int c0 = (t / 196) * 16;
        const int u_ = 2 * tid;

        for (int i = tid; i < 576; i += 256) STAGE16D(i, &g_w2a[i * 32 + c0]);
        __syncthreads();
        if (!act) return;

        const int uu = pos / 14, vv = pos % 14;
        int p0r, p1r, wu0, wu1;
        if (uu & 1) { p0r = ((uu + 1) >> 1) + 1; wu0 = 0;
                      p1r = ((uu - 1) >> 1) + 1; wu1 = 2; }
        else        { p0r = (uu >> 1) + 1;       wu0 = 1;
                      p1r = 8;                   wu1 = 0; }
        int q0r, q1r, wv0, wv1;
        if (vv & 1) { q0r = ((vv + 1) >> 1) + 1; wv0 = 0;
                      q1r = ((vv - 1) >> 1) + 1; wv1 = 2; }
        else        { q0r = (vv >> 1) + 1;       wv0 = 1;
                      q1r = 8;                   wv1 = 0; }

        const int off00 = (p0r * 9 + q0r) * PBS, wr00 = wu0 * 3 + wv0;
        const int off01 = (p0r * 9 + q1r) * PBS, wr01 = wu0 * 3 + wv1;
        const int off10 = (p1r * 9 + q0r) * PBS, wr10 = wu1 * 3 + wv0;
        const int off11 = (p1r * 9 + q1r) * PBS, wr11 = wu1 * 3 + wv1;

#pragma unroll 1
        for (int o = 0; o < 64; o++) {
            const ull* base = S2c + o * 81 * PBS + u_;
            const ull* wb = wsu + (o * 9) * 16;
            { ulonglong2 sv = ld2(base + off00); ACC16(sv, wb + wr00 * 16); }
            { ulonglong2 sv = ld2(base + off01); ACC16(sv, wb + wr01 * 16); }
            { ulonglong2 sv = ld2(base + off10); ACC16(sv, wb + wr10 * 16); }
            { ulonglong2 sv = ld2(base + off11); ACC16(sv, wb + wr11 * 16); }
        }

        const int obase = (uu + 1) * 16 + (vv + 1);
#pragma unroll
        for (int c = 0; c < 16; c++) {
            int ii = ((c0 + c) * 256 + obase) * PBS + u_;
            ulonglong2 si = ld2(S1c + ii), d1 = ld2(D1p + ii);
            ulonglong2 o;
            o.x = mul2(add2(add2(si.x, d1.x), accA[c]), hlf);
            o.y = mul2(add2(add2(si.y, d1.y), accB[c]), hlf);
            st2(S1n + ii, o);
        }
    } else if (bx < 620) {
        // ---------------- K2: s2' = 0.5*(s2 + conv2(s1)+b2 + tconv3(s3)) ----------------
        int t = bx - 424;
        const int pos = t % 49;
        const int o0 = (t / 49) * 16;
        const int u_ = 2 * tid;
        const int p = pos / 7, q = pos % 7;

        for (int i = tid; i < 288; i += 256) STAGE16D(i, &g_w2b[i * 64 + o0]);
        for (int i = tid; i < 288; i += 256) STAGE16D(288 + i, &g_w3b[i * 64 + o0]);
        __syncthreads();

        int offc[9], offt[9];
#pragma unroll
        for (int di = 0; di < 3; di++)
#pragma unroll
            for (int dj = 0; dj < 3; dj++) {
                offc[di * 3 + dj] = ((2 * p + di) * 16 + (2 * q + dj)) * PBS;
                offt[di * 3 + dj] = ((p + 2 - di) * 9 + (q + 2 - dj)) * PBS;
            }

        if (act) {
#pragma unroll 1
            for (int c = 0; c < 32; c++) {
                const ull* base = S1c + c * 256 * PBS + u_;
                const ull* wb = wsu + (c * 9) * 16;
#pragma unroll
                for (int t2 = 0; t2 < 9; t2++) {
                    ulonglong2 sv = ld2(base + offc[t2]);
                    ACC16(sv, wb + t2 * 16);
                }
            }
#pragma unroll 1
            for (int m = 0; m < 32; m++) {
                const ull* base = S3c + m * 81 * PBS + u_;
                const ull* wb = wsu + (288 + m * 9) * 16;
#pragma unroll
                for (int t2 = 0; t2 < 9; t2++) {
                    ulonglong2 sv = ld2(base + offt[t2]);
                    ACC16(sv, wb + t2 * 16);
                }
            }
        }
        __syncthreads();
        for (int i = tid; i < 288; i += 256) STAGE16D(i, &g_w3b[(288 + i) * 64 + o0]);
        __syncthreads();
        if (!act) return;
#pragma unroll 1
        for (int m = 32; m < 64; m++) {
            const ull* base = S3c + m * 81 * PBS + u_;
            const ull* wb = wsu + ((m - 32) * 9) * 16;
#pragma unroll
            for (int t2 = 0; t2 < 9; t2++) {
                ulonglong2 sv = ld2(base + offt[t2]);
                ACC16(sv, wb + t2 * 16);
            }
        }

        const int obase = (p + 1) * 9 + (q + 1);
#pragma unroll
        for (int c = 0; c < 16; c++) {
            int ii = ((o0 + c) * 81 + obase) * PBS + u_;
            ull bias = pk(b2[o0 + c]);
            ulonglong2 si = ld2(S2c + ii);
            ulonglong2 o;
            o.x = mul2(add2(add2(si.x, accA[c]), bias), hlf);
            o.y = mul2(add2(add2(si.y, accB[c]), bias), hlf);
            st2(S2n + ii, o);
        }
    } else {
        // ---------------- K3: s3' = 0.5*(s3 + conv3(s2)+b3 + W4^T s4) ----------------
        int t = bx - 620;
        const int pos = t % 49;
        const int c0 = (t / 49) * 16;
        const int u_ = 2 * tid;
        const int p = pos / 7, q = pos % 7;

        for (int i = tid; i < 576; i += 256) STAGE16D(i, &g_w3a[i * 64 + c0]);
        __syncthreads();

        if (act) {
            int off[9];
#pragma unroll
            for (int di = 0; di < 3; di++)
#pragma unroll
                for (int dj = 0; dj < 3; dj++)
                    off[di * 3 + dj] = ((p + di) * 9 + (q + dj)) * PBS;
#pragma unroll 1
            for (int o = 0; o < 64; o++) {
                const ull* base = S2c + o * 81 * PBS + u_;
                const ull* wb = wsu + (o * 9) * 16;
#pragma unroll
                for (int t2 = 0; t2 < 9; t2++) {
                    ulonglong2 sv = ld2(base + off[t2]);
                    ACC16(sv, wb + t2 * 16);
                }
            }
        }
        __syncthreads();
        for (int j = tid; j < 256; j += 256) STAGE16D(j, &g_w4r[(pos * 256 + j) * 64 + c0]);
        __syncthreads();
        if (!act) return;
#pragma unroll 1
        for (int j = 0; j < 256; j++) {
            ulonglong2 sv = ld2(S4c + j * PBS + u_);
            ACC16(sv, wsu + j * 16);
        }

        const int obase = (p + 1) * 9 + (q + 1);
#pragma unroll
        for (int c = 0; c < 16; c++) {
            int ii = ((c0 + c) * 81 + obase) * PBS + u_;
            ull bias = pk(b3[c0 + c]);
            ulonglong2 si = ld2(S3c + ii);
            ulonglong2 o;
            o.x = mul2(add2(add2(si.x, accA[c]), bias), hlf);
            o.y = mul2(add2(add2(si.y, accB[c]), bias), hlf);
            st2(S3n + ii, o);
        }
    }
}

// ============================================================================
// Small-batch forward kernels: drive = (fwd of final basis states), into [1]
// ============================================================================
__global__ void __launch_bounds__(256) fwd2s(const float* __restrict__ b2) {
    __shared__ float ws2[288 * 8];
    const int tid = threadIdx.x;
    const int o0 = blockIdx.z * 8;
    for (int i = tid; i < 288; i += 256) {
        const float* src = &g_w2b[i * 64 + o0];
        float* dst = &ws2[i * 8];
#pragma unroll
        for (int r = 0; r < 8; r++) dst[r] = src[r];
    }
    __syncthreads();

    const int bp = blockIdx.x * 256 + tid;
    if (bp >= PBS) return;
    const int pos = blockIdx.y;
    const int p = pos / 7, q = pos % 7;

    ull acc[8];
#pragma unroll
    for (int r = 0; r < 8; r++) acc[r] = 0ull;

    int off[9];
#pragma unroll
    for (int di = 0; di < 3; di++)
#pragma unroll
        for (int dj = 0; dj < 3; dj++)
            off[di * 3 + dj] = ((2 * p + di) * 16 + (2 * q + dj)) * PBS;
    const ull* __restrict__ S1 = (const ull*)g_T1[0];
#pragma unroll 2
    for (int c = 0; c < 32; c++) {
        const ull* base = S1 + c * 256 * PBS + bp;
        const float* wb = ws2 + c * 72;
#pragma unroll
        for (int t = 0; t < 9; t++) {
            ull sv = base[off[t]];
            const float* wp = wb + t * 8;
#pragma unroll
            for (int r = 0; r < 8; r++) acc[r] = fma2(sv, pk(wp[r]), acc[r]);
        }
    }

    ull* __restrict__ outp = (ull*)g_T2[1];
    const int oidx = (o0 * 81 + (p + 1) * 9 + (q + 1)) * PBS + bp;
#pragma unroll
    for (int r = 0; r < 8; r++) outp[oidx + r * (81 * PBS)] = add2(acc[r], pk(b2[o0 + r]));
}

__global__ void __launch_bounds__(256) fwd3s(const float* __restrict__ b3) {
    __shared__ ull ws3[576 * 8];
    const int tid = threadIdx.x;
    const int c0 = blockIdx.z * 8;
    const int pos = blockIdx.y;
    for (int i = tid; i < 576; i += 256) {
        const float* src = &g_w3a[i * 64 + c0];
        ull* dst = &ws3[i * 8];
#pragma unroll
        for (int r = 0; r < 8; r++) dst[r] = pk(src[r]);
    }
    __syncthreads();

    const int bp = blockIdx.x * 256 + tid;
    if (bp >= PBS) return;
    const int p = pos / 7, q = pos % 7;

    ull acc[8];
#pragma unroll
    for (int r = 0; r < 8; r++) acc[r] = 0ull;

    int off[9];
#pragma unroll
    for (int di = 0; di < 3; di++)
#pragma unroll
        for (int dj = 0; dj < 3; dj++)
            off[di * 3 + dj] = ((p + di) * 9 + (q + dj)) * PBS;
    const ull* __restrict__ S2 = (const ull*)g_T2[0];
#pragma unroll 2
    for (int o = 0; o < 64; o++) {
        const ull* base = S2 + o * 81 * PBS + bp;
        const ull* wb = ws3 + o * 72;
#pragma unroll
        for (int t = 0; t < 9; t++) {
            ull sv = base[off[t]];
            const ull* wp = wb + t * 8;
#pragma unroll
            for (int r = 0; r < 8; r++) acc[r] = fma2(sv, wp[r], acc[r]);
        }
    }

    ull* __restrict__ outp = (ull*)g_T3[1];
    const int oidx = (c0 * 81 + (p + 1) * 9 + (q + 1)) * PBS + bp;
#pragma unroll
    for (int r = 0; r < 8; r++) outp[oidx + r * (81 * PBS)] = add2(acc[r], pk(b3[c0 + r]));
}

__global__ void __launch_bounds__(256) fwd4s(const float* __restrict__ b4) {
    __shared__ ull ws[392 * 8];
    const int tid = threadIdx.x;
    const int j0 = blockIdx.y * 8;
    const int bp = blockIdx.x * 256 + tid;
    const bool act = (bp < PBS);
    const ull* __restrict__ S3 = (const ull*)g_T3[0];

    ull acc[8];
#pragma unroll
    for (int r = 0; r < 8; r++) acc[r] = 0ull;

    for (int ch = 0; ch < 8; ch++) {
        __syncthreads();
        for (int i = tid; i < 392; i += 256) {
            const float* src = &g_w4t[(ch * 392 + i) * 256 + j0];
            ull* dst = &ws[i * 8];
#pragma unroll
            for (int r = 0; r < 8; r++) dst[r] = pk(src[r]);
        }
        __syncthreads();
        if (act) {
            for (int cc = 0; cc < 8; cc++) {
                const ull* cb = S3 + ((ch * 8 + cc) * 81) * PBS + bp;
                const ull* wch = ws + cc * 392;
                int kk = 0;
#pragma unroll
                for (int pp = 1; pp <= 7; pp++) {
#pragma unroll
                    for (int qq = 1; qq <= 7; qq++) {
                        ull sv = cb[(pp * 9 + qq) * PBS];
                        const ull* wp = wch + kk * 8; kk++;
#pragma unroll
                        for (int r = 0; r < 8; r++) acc[r] = fma2(sv, wp[r], acc[r]);
                    }
                }
            }
        }
    }

    if (!act) return;
    ull* __restrict__ outp = (ull*)g_T4[1];
#pragma unroll
    for (int r = 0; r < 8; r++) outp[(j0 + r) * PBS + bp] = add2(acc[r], pk(b4[j0 + r]));
}

// ---------------- centered compact matrices A (states), H = 0.5A - G --------
__device__ __forceinline__ float state_read(int pr, int c) {
    if (pr < S1R) return g_T1[0][pr * BBS + c];
    if (pr < S1R + S2R) return g_T2[0][(pr - S1R) * BBS + c];
    if (pr < S1R + 2 * S2R) return g_T3[0][(pr - S1R - S2R) * BBS + c];
    return g_T4[0][(pr - S1R - 2 * S2R) * BBS + c];
}
__device__ __forceinline__ float drive_read(int pr, int c) {
    if (pr < S1R) return g_TD1[pr * BBS + c];
    if (pr < S1R + S2R) return g_T2[1][(pr - S1R) * BBS + c];
    if (pr < S1R + 2 * S2R) return g_T3[1][(pr - S1R - S2R) * BBS + c];
    return g_T4[1][(pr - S1R - 2 * S2R) * BBS + c];
}

__global__ void build_AH() {
    int idx = blockIdx.x * 256 + threadIdx.x;   // over RINT*785
    if (idx >= RINT * 785) return;
    int r = idx / 785, j = idx % 785;
    int pr = g_rowmap[r];
    float s0 = state_read(pr, 784);
    float d0 = drive_read(pr, 784);
    if (j < 784) {
        float a = state_read(pr, j) - s0;
        float g = drive_read(pr, j) - d0;
        g_A[r * 800 + j] = a;
        g_H[r * 800 + j] = 0.5f * a - g;
    } else {
        g_A[r * 800 + 784] = s0;
        g_H[r * 800 + 784] = 0.5f * s0 - d0;
    }
}

// ---------------- Gram GEMM: Qe = A^T H  (800x800, K = RINT) -----------------
__global__ void __launch_bounds__(256) gram_kernel() {
    __shared__ float As[16][64], Bs[16][64];
    const float* __restrict__ A = g_A;
    const float* __restrict__ B = g_H;
    float* __restrict__ C = g_Qe;
    const int tid = threadIdx.x;
    const int ti = tid / 16, tj = tid % 16;
    const int i0 = blockIdx.y * 64, j0 = blockIdx.x * 64;

    ull acc[4][2];
#pragma unroll
    for (int i = 0; i < 4; i++) { acc[i][0] = 0ull; acc[i][1] = 0ull; }

    for (int k0 = 0; k0 < RINT; k0 += 16) {
        __syncthreads();
        for (int t = tid; t < 1024; t += 256) {
            int kr = t / 64, c = t % 64;
            int ca = i0 + c, cb = j0 + c;
            As[kr][c] = (ca < 800) ? A[(k0 + kr) * 800 + ca] : 0.f;
            Bs[kr][c] = (cb < 800) ? B[(k0 + kr) * 800 + cb] : 0.f;
        }
        __syncthreads();
#pragma unroll 4
        for (int k = 0; k < 16; k++) {
            const float* ar = &As[k][ti * 4];
            const ull* br = reinterpret_cast<const ull*>(&Bs[k][tj * 4]);
            ull b0 = br[0], b1 = br[1];
#pragma unroll
            for (int i = 0; i < 4; i++) {
                ull av = pk(ar[i]);
                acc[i][0] = fma2(av, b0, acc[i][0]);
                acc[i][1] = fma2(av, b1, acc[i][1]);
            }
        }
    }

#pragma unroll
    for (int i = 0; i < 4; i++) {
        int row = i0 + ti * 4 + i;
        int col = j0 + tj * 4;
        if (row < 800 && col < 800) {
            ull* dst = reinterpret_cast<ull*>(&C[row * 800 + col]);
            dst[0] = acc[i][0];
            dst[1] = acc[i][1];
        }
    }
}

// ---------------- Z = Qe * XTh  (800 x 4096) ----------------
__global__ void __launch_bounds__(256) zgemm() {
    __shared__ ull smw[200 * 16];    // 25.6 KB
    const int tid = threadIdx.x;
    const int bx = blockIdx.x;
    const int bslice = bx & 3;
    const int row0 = (bx >> 2) * 16;
    const int u = bslice * 512 + 2 * tid;

    ull accA[16], accB[16];
#pragma unroll
    for (int c = 0; c < 16; c++) { accA[c] = 0ull; accB[c] = 0ull; }

    const ull* __restrict__ XT2 = (const ull*)g_XTh;
    for (int ch = 0; ch < 4; ch++) {
        __syncthreads();
        for (int idx = tid; idx < 16 * 200; idx += 256) {
            int r = idx / 200, k = idx % 200;
            smw[k * 16 + r] = pk(g_Qe[(row0 + r) * 800 + ch * 200 + k]);
        }
        __syncthreads();
#pragma unroll 1
        for (int k = 0; k < 200; k++) {
            ulonglong2 sv = ld2(XT2 + (ch * 200 + k) * PB + u);
            const ull* wp = &smw[k * 16];
            ACC16(sv, wp);
        }
    }

    ull* __restrict__ Z = (ull*)g_Z;
#pragma unroll
    for (int c = 0; c < 16; c++) {
        ulonglong2 o; o.x = accA[c]; o.y = accB[c];
        st2(Z + (row0 + c) * PB + u, o);
    }
}

// ---------------- final energy: E = 0.5|x|^2 - vb.x + xh^T Qe xh ------------
__global__ void energy_final(const float* __restrict__ vb, float* __restrict__ out) {
    int b = blockIdx.x * 256 + threadIdx.x;
    double e = 0.0;
    for (int i = 0; i < 784; i++) {
        float xv = g_XTh[i * BB + b];
        float term = xv * (0.5f * xv - vb[i] + g_Z[i * BB + b]);
        e += (double)term;
    }
    e += (double)g_Z[784 * BB + b];
    out[b] = (float)e;
}

// ---------------- launcher ----------------
extern "C" void kernel_launch(void* const* d_in, const int* in_sizes, int n_in,
                              void* d_out, int out_size) {
    const float* x  = (const float*)d_in[0];
    const float* vb = (const float*)d_in[1];
    const float* w1 = (const float*)d_in[2];
    const float* b1 = (const float*)d_in[3];
    const float* w2 = (const float*)d_in[4];
    const float* b2 = (const float*)d_in[5];
    const float* w3 = (const float*)d_in[6];
    const float* b3 = (const float*)d_in[7];
    const float* w4 = (const float*)d_in[8];
    const float* b4 = (const float*)d_in[9];
    float* out = (float*)d_out;

    cudaFuncSetAttribute(step_small, cudaFuncAttributeMaxDynamicSharedMemorySize, STEP_SMEM);

    zero_small<<<2048, 256>>>();
    basis_x<<<(784 * BBS + 255) / 256, 256>>>();
    build_rowmap<<<(RINT + 255) / 256, 256>>>();
    transpose_x<<<dim3(25, 128), dim3(32, 8)>>>(x);
    xh_one<<<16, 256>>>();
    prep_weights<<<1024, 256>>>(w2, w3, w4);
    compute_d1_small<<<dim3((BBS + 255) / 256, 196, 32), 256>>>(w1, b1);

    // 50-step relaxation on 784 basis images + zero image (final in buffer 0)
    int cs = 0;
    for (int t = 0; t < 50; t++) {
        step_small<<<STEP_GRID, 256, STEP_SMEM>>>(cs, b2, b3, b4);
        cs ^= 1;
    }

    // drive vectors: forward pass of final basis states into buffers [1]
    fwd2s<<<dim3(2, 49, 8), 256>>>(b2);
    fwd3s<<<dim3(2, 49, 8), 256>>>(b3);
    fwd4s<<<dim3(2, 32, 1), 256>>>(b4);

    // quadratic form: A (states), H = 0.5A - G (drives); Qe = A^T H (one GEMM)
    build_AH<<<(RINT * 785 + 255) / 256, 256>>>();
    gram_kernel<<<dim3(13, 13), 256>>>();

    // evaluate: Z = Qe * XTh, then E_b per sample
    zgemm<<<(800 / 16) * 4, 256>>>();
    energy_final<<<16, 256>>>(vb, out);
}